// round 8
// baseline (speedup 1.0000x reference)
#include <cuda_runtime.h>

// Problem constants
#define NN 262144
#define DD 128
#define KK 256
#define LL 4
#define TM 32           // rows per CTA
#define NTHREADS 256    // 8 warps, each owns 4 rows
#define KP 129          // padded k-row stride in smem (odd -> conflict-free both ways)

// Output layout: (qhard[N,D], qsoft[N,D], soft_dist, hard_dist, joint_center, error, hard_code[N,L])
#define QH_OFF   0L
#define QS_OFF   ((long)NN * DD)
#define SC_OFF   (2L * NN * DD)
#define CODE_OFF (2L * NN * DD + 4)

// smem floats: codes K*KP + resid TM*D + x TM*D + qsoft TM*D + P TM*K + cc K + red 32 ; then TM*L ints
#define SMEM_FLOATS (KK*KP + 3*TM*DD + TM*KK + KK + 32)
#define SMEM_BYTES  (SMEM_FLOATS*4 + TM*LL*4)

__global__ void rvq_zero_scalars(float* out) {
    if (threadIdx.x < 4) out[SC_OFF + threadIdx.x] = 0.0f;
}

__global__ __launch_bounds__(NTHREADS, 1)
void rvq_kernel(const float* __restrict__ x_g,
                const float* __restrict__ cb_g,
                float* __restrict__ out) {
    extern __shared__ float sm[];
    float* sC   = sm;                       // [KK][KP]
    float* sR   = sC + KK*KP;               // residual [TM][DD]
    float* sX   = sR + TM*DD;               // original x [TM][DD]
    float* sQ   = sX + TM*DD;               // qsoft accum [TM][DD]
    float* sP   = sQ + TM*DD;               // exp weights [TM][KK]
    float* sCC  = sP + TM*KK;               // code norms [KK]
    float* sRed = sCC + KK;                 // 4 x 8 warp partials
    int*   sCode= (int*)(sRed + 32);        // [TM][LL]

    const int tid  = threadIdx.x;
    const int lane = tid & 31;
    const int w    = tid >> 5;
    const long rowBase = (long)blockIdx.x * TM;

    // ---- load tile: residual = x, qsoft = 0 ----
    for (int i = tid; i < TM*DD; i += NTHREADS) {
        float v = x_g[rowBase*DD + i];
        sR[i] = v; sX[i] = v; sQ[i] = 0.0f;
    }
    __syncthreads();

    float* Rw = sR + (w*4)*DD;   // this warp's 4 rows
    float* Xw = sX + (w*4)*DD;
    float* Qw = sQ + (w*4)*DD;

    // ---- initial rr = ||residual_row||^2 (per warp-row) ----
    float rr[4];
    #pragma unroll
    for (int r = 0; r < 4; r++) {
        float s = 0.0f;
        #pragma unroll
        for (int i = 0; i < 4; i++) { float v = Rw[r*DD + lane + 32*i]; s += v*v; }
        #pragma unroll
        for (int o = 16; o > 0; o >>= 1) s += __shfl_xor_sync(0xffffffffu, s, o);
        rr[r] = s;
    }

    float softAcc = 0.0f, hardAcc = 0.0f, errAcc = 0.0f;

    for (int level = 0; level < LL; level++) {
        // ---- stage this level's codebook into smem [k][KP] ----
        __syncthreads();   // prior level finished reading sC
        const float* cbl = cb_g + (long)level * KK * DD;
        for (int i = tid; i < KK*DD; i += NTHREADS) {
            int k = i >> 7, d = i & 127;
            sC[k*KP + d] = cbl[i];          // coalesced LDG, conflict-free STS
        }
        __syncthreads();

        // ---- cc[k] = ||c_k||^2 ----
        for (int k = w; k < KK; k += 8) {
            float s = 0.0f;
            #pragma unroll
            for (int i = 0; i < 4; i++) { float v = sC[k*KP + lane + 32*i]; s += v*v; }
            #pragma unroll
            for (int o = 16; o > 0; o >>= 1) s += __shfl_xor_sync(0xffffffffu, s, o);
            if (lane == 0) sCC[k] = s;
        }
        __syncthreads();

        // ---- GEMM1: dot[r][k] = residual_r . c_k  (fp32, fidelity-critical) ----
        float acc[4][8];
        #pragma unroll
        for (int r = 0; r < 4; r++)
            #pragma unroll
            for (int j = 0; j < 8; j++) acc[r][j] = 0.0f;

        const float* Cb = sC + lane*KP;     // lane's base code row; + j*32*KP + d
        #pragma unroll 4
        for (int d = 0; d < DD; d++) {
            float r0 = Rw[0*DD + d], r1 = Rw[1*DD + d];   // broadcast LDS
            float r2 = Rw[2*DD + d], r3 = Rw[3*DD + d];
            #pragma unroll
            for (int j = 0; j < 8; j++) {
                float c = Cb[j*32*KP + d];                 // conflict-free (bank = lane)
                acc[0][j] = __fmaf_rn(r0, c, acc[0][j]);
                acc[1][j] = __fmaf_rn(r1, c, acc[1][j]);
                acc[2][j] = __fmaf_rn(r2, c, acc[2][j]);
                acc[3][j] = __fmaf_rn(r3, c, acc[3][j]);
            }
        }

        // ---- per-row: d2, max, norm=d2/max, argmin(first idx), softmax weights ----
        int   codes_r[4];
        float invz[4];
        #pragma unroll
        for (int r = 0; r < 4; r++) {
            float d2v[8];
            float mx = -1e30f;
            #pragma unroll
            for (int j = 0; j < 8; j++) {
                float t  = __fadd_rn(rr[r], sCC[lane + 32*j]);
                float d2 = __fmaf_rn(-2.0f, acc[r][j], t);   // (rr+cc) - 2*dot, 2*dot exact
                d2v[j] = d2;
                mx = fmaxf(mx, d2);
            }
            #pragma unroll
            for (int o = 16; o > 0; o >>= 1) mx = fmaxf(mx, __shfl_xor_sync(0xffffffffu, mx, o));

            float bestv = 1e30f; int bestk = KK;
            #pragma unroll
            for (int j = 0; j < 8; j++) {
                float nv = __fdiv_rn(d2v[j], mx);            // IEEE div like the reference
                d2v[j] = nv;
                int k = lane + 32*j;
                if (nv < bestv || (nv == bestv && k < bestk)) { bestv = nv; bestk = k; }
            }
            #pragma unroll
            for (int o = 16; o > 0; o >>= 1) {
                float ov = __shfl_xor_sync(0xffffffffu, bestv, o);
                int   ok = __shfl_xor_sync(0xffffffffu, bestk, o);
                if (ov < bestv || (ov == bestv && ok < bestk)) { bestv = ov; bestk = ok; }
            }

            float z = 0.0f;
            float* Prow = sP + (w*4 + r)*KK;
            #pragma unroll
            for (int j = 0; j < 8; j++) {
                float e = __expf(bestv - d2v[j]);            // dist - max(dist); slack path
                z += e;
                Prow[lane + 32*j] = e;
            }
            #pragma unroll
            for (int o = 16; o > 0; o >>= 1) z += __shfl_xor_sync(0xffffffffu, z, o);
            invz[r]   = 1.0f / z;
            codes_r[r] = bestk;
            if (lane == 0) sCode[(w*4 + r)*LL + level] = bestk;
        }

        // ---- GEMM2: qsoft += (e @ C) / Z   (slack path) ----
        {
            float a[4][4];
            #pragma unroll
            for (int r = 0; r < 4; r++)
                #pragma unroll
                for (int i = 0; i < 4; i++) a[r][i] = 0.0f;

            const float* Cb2 = sC + lane;                    // + k*KP + 32*i, conflict-free
            const float* P0  = sP + (w*4)*KK;
            #pragma unroll 2
            for (int k = 0; k < KK; k++) {
                float c0 = Cb2[k*KP],      c1 = Cb2[k*KP + 32];
                float c2 = Cb2[k*KP + 64], c3 = Cb2[k*KP + 96];
                #pragma unroll
                for (int r = 0; r < 4; r++) {
                    float p = P0[r*KK + k];                  // broadcast
                    a[r][0] = __fmaf_rn(p, c0, a[r][0]);
                    a[r][1] = __fmaf_rn(p, c1, a[r][1]);
                    a[r][2] = __fmaf_rn(p, c2, a[r][2]);
                    a[r][3] = __fmaf_rn(p, c3, a[r][3]);
                }
            }
            #pragma unroll
            for (int r = 0; r < 4; r++) {
                float iz = invz[r];
                #pragma unroll
                for (int i = 0; i < 4; i++)
                    Qw[r*DD + lane + 32*i] += a[r][i] * iz;
            }
        }

        // ---- residual -= codes[code]; rr_new; hard-dist partial ----
        float hardLevel = 0.0f;
        #pragma unroll
        for (int r = 0; r < 4; r++) {
            const float* crow = sC + codes_r[r]*KP;
            float s = 0.0f;
            #pragma unroll
            for (int i = 0; i < 4; i++) {
                int d = lane + 32*i;
                float nv = Rw[r*DD + d] - crow[d];
                Rw[r*DD + d] = nv;
                s += nv*nv;
            }
            #pragma unroll
            for (int o = 16; o > 0; o >>= 1) s += __shfl_xor_sync(0xffffffffu, s, o);
            rr[r] = s;
            hardLevel += s;                                   // ||x - qhard||^2 == ||residual||^2
        }
        hardAcc += hardLevel;
        if (level == LL - 1) errAcc = hardLevel;

        // ---- soft-dist partial: ||x - qsoft||^2 ----
        float sp = 0.0f;
        #pragma unroll
        for (int r = 0; r < 4; r++)
            #pragma unroll
            for (int i = 0; i < 4; i++) {
                int d = lane + 32*i;
                float dv = Xw[r*DD + d] - Qw[r*DD + d];
                sp += dv*dv;
            }
        #pragma unroll
        for (int o = 16; o > 0; o >>= 1) sp += __shfl_xor_sync(0xffffffffu, sp, o);
        softAcc += sp;
    } // levels

    // ---- joint_center partial: (qsoft - qhard)^2, qhard = x - residual ----
    float jp = 0.0f;
    #pragma unroll
    for (int r = 0; r < 4; r++)
        #pragma unroll
        for (int i = 0; i < 4; i++) {
            int d = lane + 32*i;
            float qh = Xw[r*DD + d] - Rw[r*DD + d];
            float dv = Qw[r*DD + d] - qh;
            jp += dv*dv;
        }
    #pragma unroll
    for (int o = 16; o > 0; o >>= 1) jp += __shfl_xor_sync(0xffffffffu, jp, o);

    if (lane == 0) {
        sRed[w]      = softAcc;
        sRed[8 + w]  = hardAcc;
        sRed[16 + w] = errAcc;
        sRed[24 + w] = jp;
    }
    __syncthreads();
    if (tid == 0) {
        float s = 0, h = 0, e = 0, j = 0;
        for (int i = 0; i < 8; i++) { s += sRed[i]; h += sRed[8+i]; e += sRed[16+i]; j += sRed[24+i]; }
        atomicAdd(out + SC_OFF + 0, s / (float)NN);                 // soft_dist
        atomicAdd(out + SC_OFF + 1, h / (float)NN);                 // hard_dist
        atomicAdd(out + SC_OFF + 2, j / ((float)NN * (float)DD));   // joint_center
        atomicAdd(out + SC_OFF + 3, e / (float)NN);                 // error
    }

    // ---- write qhard, qsoft, hard_code ----
    for (int i = tid; i < TM*DD; i += NTHREADS) {
        out[QH_OFF + rowBase*DD + i] = sX[i] - sR[i];
        out[QS_OFF + rowBase*DD + i] = sQ[i];
    }
    for (int i = tid; i < TM*LL; i += NTHREADS)
        out[CODE_OFF + rowBase*LL + i] = (float)sCode[i];
}

extern "C" void kernel_launch(void* const* d_in, const int* in_sizes, int n_in,
                              void* d_out, int out_size) {
    (void)in_sizes; (void)n_in; (void)out_size;
    const float* x  = (const float*)d_in[0];
    const float* cb = (const float*)d_in[1];
    float* out = (float*)d_out;

    cudaFuncSetAttribute(rvq_kernel, cudaFuncAttributeMaxDynamicSharedMemorySize, SMEM_BYTES);

    rvq_zero_scalars<<<1, 32>>>(out);
    rvq_kernel<<<NN/TM, NTHREADS, SMEM_BYTES>>>(x, cb, out);
}

// round 9
// speedup vs baseline: 1.4476x; 1.4476x over previous
#include <cuda_runtime.h>

// Problem constants
#define NN 262144
#define DD 128
#define KK 256
#define LL 4
#define TM 32           // rows per CTA
#define NTHREADS 256    // 8 warps, each owns 4 rows
#define KP 130          // padded k-row stride (even -> 8B-aligned float2, half-warp conflict-free)

// Output layout: (qhard[N,D], qsoft[N,D], soft_dist, hard_dist, joint_center, error, hard_code[N,L])
#define QH_OFF   0L
#define QS_OFF   ((long)NN * DD)
#define SC_OFF   (2L * NN * DD)
#define CODE_OFF (2L * NN * DD + 4)

#define SMEM_FLOATS (KK*KP + 3*TM*DD + TM*KK + KK + 32)
#define SMEM_BYTES  (SMEM_FLOATS*4 + TM*LL*4)

typedef unsigned long long u64;

__device__ __forceinline__ u64 fma2(u64 a, u64 b, u64 c) {
    u64 d;
    asm("fma.rn.f32x2 %0, %1, %2, %3;" : "=l"(d) : "l"(a), "l"(b), "l"(c));
    return d;
}
__device__ __forceinline__ u64 pack2(float x, float y) {
    u64 d;
    asm("mov.b64 %0, {%1, %2};" : "=l"(d) : "f"(x), "f"(y));
    return d;
}
__device__ __forceinline__ float2 unpack2(u64 v) {
    float2 f;
    asm("mov.b64 {%0, %1}, %2;" : "=f"(f.x), "=f"(f.y) : "l"(v));
    return f;
}
__device__ __forceinline__ u64 lds64(const float* p) {
    return *(const u64*)p;
}

__global__ void rvq_zero_scalars(float* out) {
    if (threadIdx.x < 4) out[SC_OFF + threadIdx.x] = 0.0f;
}

__global__ __launch_bounds__(NTHREADS, 1)
void rvq_kernel(const float* __restrict__ x_g,
                const float* __restrict__ cb_g,
                float* __restrict__ out) {
    extern __shared__ float sm[];
    float* sC   = sm;                       // [KK][KP]
    float* sR   = sC + KK*KP;               // residual [TM][DD]
    float* sX   = sR + TM*DD;               // original x [TM][DD]
    float* sQ   = sX + TM*DD;               // qsoft accum [TM][DD]
    float* sP   = sQ + TM*DD;               // exp weights [TM][KK]
    float* sCC  = sP + TM*KK;               // code norms [KK]
    float* sRed = sCC + KK;                 // 4 x 8 warp partials
    int*   sCode= (int*)(sRed + 32);        // [TM][LL]

    const int tid  = threadIdx.x;
    const int lane = tid & 31;
    const int w    = tid >> 5;
    const long rowBase = (long)blockIdx.x * TM;

    // ---- load tile (float4): residual = x, qsoft = 0 ----
    {
        const float4* xg4 = (const float4*)(x_g + rowBase*DD);
        float4* r4 = (float4*)sR; float4* x4 = (float4*)sX; float4* q4 = (float4*)sQ;
        const float4 z4 = make_float4(0.f, 0.f, 0.f, 0.f);
        for (int i = tid; i < (TM*DD)/4; i += NTHREADS) {
            float4 v = xg4[i];
            r4[i] = v; x4[i] = v; q4[i] = z4;
        }
    }
    __syncthreads();

    float* Rw = sR + (w*4)*DD;   // this warp's 4 rows
    float* Xw = sX + (w*4)*DD;
    float* Qw = sQ + (w*4)*DD;

    // ---- initial rr = ||residual_row||^2 ----
    float rr[4];
    #pragma unroll
    for (int r = 0; r < 4; r++) {
        float4 v = *(const float4*)(Rw + r*DD + 4*lane);
        float s = v.x*v.x + v.y*v.y + v.z*v.z + v.w*v.w;
        #pragma unroll
        for (int o = 16; o > 0; o >>= 1) s += __shfl_xor_sync(0xffffffffu, s, o);
        rr[r] = s;
    }

    float softAcc = 0.0f, hardAcc = 0.0f, errAcc = 0.0f;

    for (int level = 0; level < LL; level++) {
        // ---- stage this level's codebook into smem [k][KP] (LDG.128) ----
        __syncthreads();   // prior level finished reading sC
        const float4* cbl4 = (const float4*)(cb_g + (long)level * KK * DD);
        for (int i = tid; i < (KK*DD)/4; i += NTHREADS) {
            float4 v = cbl4[i];
            int k = i >> 5;            // (i*4)/128
            int d = (i & 31) << 2;     // (i*4)%128
            float* dst = sC + k*KP + d;
            *(float2*)(dst)     = make_float2(v.x, v.y);
            *(float2*)(dst + 2) = make_float2(v.z, v.w);
        }
        __syncthreads();

        // ---- cc[k] = ||c_k||^2 (float2 loads, half-warp conflict-free) ----
        for (int k = w; k < KK; k += 8) {
            float2 a = *(const float2*)(sC + k*KP + 2*lane);
            float2 b = *(const float2*)(sC + k*KP + 64 + 2*lane);
            float s = a.x*a.x + a.y*a.y + b.x*b.x + b.y*b.y;
            #pragma unroll
            for (int o = 16; o > 0; o >>= 1) s += __shfl_xor_sync(0xffffffffu, s, o);
            if (lane == 0) sCC[k] = s;
        }
        __syncthreads();

        // ---- GEMM1 (f32x2): dot[r][k] = residual_r . c_k ----
        u64 acc[4][8];
        #pragma unroll
        for (int r = 0; r < 4; r++)
            #pragma unroll
            for (int j = 0; j < 8; j++) acc[r][j] = 0ull;

        const float* Cb = sC + lane*KP;
        #pragma unroll 2
        for (int d = 0; d < DD; d += 4) {
            ulonglong2 R0 = *(const ulonglong2*)(Rw + 0*DD + d);   // {d,d+1},{d+2,d+3}
            ulonglong2 R1 = *(const ulonglong2*)(Rw + 1*DD + d);
            ulonglong2 R2 = *(const ulonglong2*)(Rw + 2*DD + d);
            ulonglong2 R3 = *(const ulonglong2*)(Rw + 3*DD + d);
            #pragma unroll
            for (int j = 0; j < 8; j++) {
                const float* Cj = Cb + j*32*KP + d;
                u64 cA = lds64(Cj);
                u64 cB = lds64(Cj + 2);
                acc[0][j] = fma2(R0.x, cA, acc[0][j]);
                acc[1][j] = fma2(R1.x, cA, acc[1][j]);
                acc[2][j] = fma2(R2.x, cA, acc[2][j]);
                acc[3][j] = fma2(R3.x, cA, acc[3][j]);
                acc[0][j] = fma2(R0.y, cB, acc[0][j]);
                acc[1][j] = fma2(R1.y, cB, acc[1][j]);
                acc[2][j] = fma2(R2.y, cB, acc[2][j]);
                acc[3][j] = fma2(R3.y, cB, acc[3][j]);
            }
        }

        // ---- per-row: d2, max, norm=d2/max, argmin(first idx), softmax weights ----
        int   codes_r[4];
        float invz[4];
        #pragma unroll
        for (int r = 0; r < 4; r++) {
            float d2v[8];
            float mx = -1e30f;
            #pragma unroll
            for (int j = 0; j < 8; j++) {
                float2 f = unpack2(acc[r][j]);
                float dot = f.x + f.y;
                float t  = __fadd_rn(rr[r], sCC[lane + 32*j]);
                float d2 = __fmaf_rn(-2.0f, dot, t);
                d2v[j] = d2;
                mx = fmaxf(mx, d2);
            }
            #pragma unroll
            for (int o = 16; o > 0; o >>= 1) mx = fmaxf(mx, __shfl_xor_sync(0xffffffffu, mx, o));

            float bestv = 1e30f; int bestk = KK;
            #pragma unroll
            for (int j = 0; j < 8; j++) {
                float nv = __fdiv_rn(d2v[j], mx);            // IEEE div like the reference
                d2v[j] = nv;
                int k = lane + 32*j;
                if (nv < bestv || (nv == bestv && k < bestk)) { bestv = nv; bestk = k; }
            }
            #pragma unroll
            for (int o = 16; o > 0; o >>= 1) {
                float ov = __shfl_xor_sync(0xffffffffu, bestv, o);
                int   ok = __shfl_xor_sync(0xffffffffu, bestk, o);
                if (ov < bestv || (ov == bestv && ok < bestk)) { bestv = ov; bestk = ok; }
            }

            float z = 0.0f;
            float* Prow = sP + (w*4 + r)*KK;
            #pragma unroll
            for (int j = 0; j < 8; j++) {
                float e = __expf(bestv - d2v[j]);
                z += e;
                Prow[lane + 32*j] = e;
            }
            #pragma unroll
            for (int o = 16; o > 0; o >>= 1) z += __shfl_xor_sync(0xffffffffu, z, o);
            invz[r]    = 1.0f / z;
            codes_r[r] = bestk;
            if (lane == 0) sCode[(w*4 + r)*LL + level] = bestk;
        }

        // ---- GEMM2 (f32x2): qsoft += (e @ C) / Z ; thread owns d-pairs 2*lane(+64) ----
        {
            u64 a2[4][2];
            #pragma unroll
            for (int r = 0; r < 4; r++) { a2[r][0] = 0ull; a2[r][1] = 0ull; }

            const float* Cb2 = sC + 2*lane;
            const float* P0  = sP + (w*4)*KK;
            #pragma unroll 1
            for (int k = 0; k < KK; k += 4) {
                float4 q0 = *(const float4*)(P0 + 0*KK + k);
                float4 q1 = *(const float4*)(P0 + 1*KK + k);
                float4 q2 = *(const float4*)(P0 + 2*KK + k);
                float4 q3 = *(const float4*)(P0 + 3*KK + k);
                float p0[4] = {q0.x, q0.y, q0.z, q0.w};
                float p1[4] = {q1.x, q1.y, q1.z, q1.w};
                float p2[4] = {q2.x, q2.y, q2.z, q2.w};
                float p3[4] = {q3.x, q3.y, q3.z, q3.w};
                #pragma unroll
                for (int kk = 0; kk < 4; kk++) {
                    const float* Ck = Cb2 + (k + kk)*KP;
                    u64 c0 = lds64(Ck);
                    u64 c1 = lds64(Ck + 64);
                    u64 pp0 = pack2(p0[kk], p0[kk]);
                    u64 pp1 = pack2(p1[kk], p1[kk]);
                    u64 pp2 = pack2(p2[kk], p2[kk]);
                    u64 pp3 = pack2(p3[kk], p3[kk]);
                    a2[0][0] = fma2(pp0, c0, a2[0][0]);  a2[0][1] = fma2(pp0, c1, a2[0][1]);
                    a2[1][0] = fma2(pp1, c0, a2[1][0]);  a2[1][1] = fma2(pp1, c1, a2[1][1]);
                    a2[2][0] = fma2(pp2, c0, a2[2][0]);  a2[2][1] = fma2(pp2, c1, a2[2][1]);
                    a2[3][0] = fma2(pp3, c0, a2[3][0]);  a2[3][1] = fma2(pp3, c1, a2[3][1]);
                }
            }
            #pragma unroll
            for (int r = 0; r < 4; r++) {
                float iz = invz[r];
                #pragma unroll
                for (int i = 0; i < 2; i++) {
                    float2 f = unpack2(a2[r][i]);
                    float2* qp = (float2*)(Qw + r*DD + 64*i + 2*lane);
                    float2 cur = *qp;
                    cur.x += f.x * iz;
                    cur.y += f.y * iz;
                    *qp = cur;
                }
            }
        }

        // ---- residual -= codes[code]; rr_new; hard-dist partial ----
        float hardLevel = 0.0f;
        #pragma unroll
        for (int r = 0; r < 4; r++) {
            const float* crow = sC + codes_r[r]*KP;
            float s = 0.0f;
            #pragma unroll
            for (int i = 0; i < 2; i++) {
                int d = 64*i + 2*lane;
                float2 rv = *(float2*)(Rw + r*DD + d);
                float2 cv = *(const float2*)(crow + d);
                rv.x -= cv.x; rv.y -= cv.y;
                *(float2*)(Rw + r*DD + d) = rv;
                s += rv.x*rv.x + rv.y*rv.y;
            }
            #pragma unroll
            for (int o = 16; o > 0; o >>= 1) s += __shfl_xor_sync(0xffffffffu, s, o);
            rr[r] = s;
            hardLevel += s;                                   // ||x - qhard||^2 == ||residual||^2
        }
        hardAcc += hardLevel;
        if (level == LL - 1) errAcc = hardLevel;

        // ---- soft-dist partial: ||x - qsoft||^2 (float4) ----
        float sp = 0.0f;
        #pragma unroll
        for (int r = 0; r < 4; r++) {
            float4 xv = *(const float4*)(Xw + r*DD + 4*lane);
            float4 qv = *(const float4*)(Qw + r*DD + 4*lane);
            float a0 = xv.x - qv.x, a1 = xv.y - qv.y, a2_ = xv.z - qv.z, a3 = xv.w - qv.w;
            sp += a0*a0 + a1*a1 + a2_*a2_ + a3*a3;
        }
        #pragma unroll
        for (int o = 16; o > 0; o >>= 1) sp += __shfl_xor_sync(0xffffffffu, sp, o);
        softAcc += sp;
    } // levels

    // ---- joint_center partial: (qsoft - qhard)^2, qhard = x - residual ----
    float jp = 0.0f;
    #pragma unroll
    for (int r = 0; r < 4; r++) {
        float4 xv = *(const float4*)(Xw + r*DD + 4*lane);
        float4 rv = *(const float4*)(Rw + r*DD + 4*lane);
        float4 qv = *(const float4*)(Qw + r*DD + 4*lane);
        float d0 = qv.x - (xv.x - rv.x);
        float d1 = qv.y - (xv.y - rv.y);
        float d2 = qv.z - (xv.z - rv.z);
        float d3 = qv.w - (xv.w - rv.w);
        jp += d0*d0 + d1*d1 + d2*d2 + d3*d3;
    }
    #pragma unroll
    for (int o = 16; o > 0; o >>= 1) jp += __shfl_xor_sync(0xffffffffu, jp, o);

    if (lane == 0) {
        sRed[w]      = softAcc;
        sRed[8 + w]  = hardAcc;
        sRed[16 + w] = errAcc;
        sRed[24 + w] = jp;
    }
    __syncthreads();
    if (tid == 0) {
        float s = 0, h = 0, e = 0, j = 0;
        for (int i = 0; i < 8; i++) { s += sRed[i]; h += sRed[8+i]; e += sRed[16+i]; j += sRed[24+i]; }
        atomicAdd(out + SC_OFF + 0, s / (float)NN);                 // soft_dist
        atomicAdd(out + SC_OFF + 1, h / (float)NN);                 // hard_dist
        atomicAdd(out + SC_OFF + 2, j / ((float)NN * (float)DD));   // joint_center
        atomicAdd(out + SC_OFF + 3, e / (float)NN);                 // error
    }

    // ---- write qhard, qsoft (float4), hard_code ----
    {
        const float4* x4 = (const float4*)sX;
        const float4* r4 = (const float4*)sR;
        const float4* q4 = (const float4*)sQ;
        float4* qh4 = (float4*)(out + QH_OFF + rowBase*DD);
        float4* qs4 = (float4*)(out + QS_OFF + rowBase*DD);
        for (int i = tid; i < (TM*DD)/4; i += NTHREADS) {
            float4 xv = x4[i], rv = r4[i];
            qh4[i] = make_float4(xv.x - rv.x, xv.y - rv.y, xv.z - rv.z, xv.w - rv.w);
            qs4[i] = q4[i];
        }
    }
    for (int i = tid; i < TM*LL; i += NTHREADS)
        out[CODE_OFF + rowBase*LL + i] = (float)sCode[i];
}

extern "C" void kernel_launch(void* const* d_in, const int* in_sizes, int n_in,
                              void* d_out, int out_size) {
    (void)in_sizes; (void)n_in; (void)out_size;
    const float* x  = (const float*)d_in[0];
    const float* cb = (const float*)d_in[1];
    float* out = (float*)d_out;

    cudaFuncSetAttribute(rvq_kernel, cudaFuncAttributeMaxDynamicSharedMemorySize, SMEM_BYTES);

    rvq_zero_scalars<<<1, 32>>>(out);
    rvq_kernel<<<NN/TM, NTHREADS, SMEM_BYTES>>>(x, cb, out);
}